// round 6
// baseline (speedup 1.0000x reference)
#include <cuda_runtime.h>
#include <math.h>

#define NP     4096
#define TOTAL  65536              // points per tensor (16*4096)
#define ROWS   32                 // rows: 0-15 = x batches, 16-31 = y batches
#define NB     256
#define LOV    (-5.0f)
#define HIV    (5.0f)
#define WBIN   ((HIV - LOV) / NB)
#define INVW   ((float)NB / (HIV - LOV))
#define WMINW  448                // min points in a warp's window
#define BT     128                // phase1 block threads
#define CBLOCKS (2 * TOTAL / BT)  // 1024
#define FULLM  0xFFFFFFFFu

__device__ float4 g_sorted[2 * TOTAL];        // bucketed {x,y,z,0.5|p|^2}
__device__ int    g_hist8[ROWS][8][NB];       // per-segment histograms
__device__ int    g_cursor[ROWS][NB];
__device__ int    g_binstart[ROWS][NB + 1];
__device__ float  g_partial[CBLOCKS];

__device__ __forceinline__ int binof(float v) {
    int b = (int)((v - LOV) * INVW);
    return min(max(b, 0), NB - 1);
}

// 256 blocks: 8 segments per row, 512 points each. Plain stores -> no zero pass.
__global__ __launch_bounds__(256) void hist_kernel(const float* __restrict__ x,
                                                   const float* __restrict__ y) {
    int row = blockIdx.x >> 3, seg = blockIdx.x & 7;
    const float* src = ((row >= 16) ? y : x) + (size_t)(row & 15) * NP * 3;
    __shared__ int h[NB];
    int tid = threadIdx.x;
    h[tid] = 0;
    __syncthreads();
    int p0 = seg * 512 + tid * 2;
    atomicAdd(&h[binof(src[3 * p0])], 1);
    atomicAdd(&h[binof(src[3 * (p0 + 1)])], 1);
    __syncthreads();
    g_hist8[row][seg][tid] = h[tid];
}

// 32 blocks: sum 8 segment histos, Hillis-Steele scan, zero cursors.
__global__ __launch_bounds__(NB) void prefix_kernel() {
    int row = blockIdx.x, tid = threadIdx.x;
    __shared__ int s[NB];
    int v = 0;
    #pragma unroll
    for (int k = 0; k < 8; k++) v += g_hist8[row][k][tid];
    s[tid] = v;
    __syncthreads();
    #pragma unroll
    for (int off = 1; off < NB; off <<= 1) {
        int t = (tid >= off) ? s[tid - off] : 0;
        __syncthreads();
        s[tid] += t;
        __syncthreads();
    }
    g_binstart[row][tid] = s[tid] - v;
    g_cursor[row][tid] = 0;
    if (tid == NB - 1) g_binstart[row][NB] = s[tid];
}

__global__ __launch_bounds__(256) void scatter_kernel(const float* __restrict__ x,
                                                      const float* __restrict__ y) {
    int row = blockIdx.x >> 3, seg = blockIdx.x & 7;
    const float* src = ((row >= 16) ? y : x) + (size_t)(row & 15) * NP * 3;
    int p0 = seg * 512 + threadIdx.x * 2;
    const float2* s2 = (const float2*)(src + 3 * p0);
    float2 ab = s2[0], ca = s2[1], bc = s2[2];
    float4* dst = g_sorted + (size_t)row * NP;
    {
        int bin = binof(ab.x);
        int pos = g_binstart[row][bin] + atomicAdd(&g_cursor[row][bin], 1);
        dst[pos] = make_float4(ab.x, ab.y, ca.x,
                               0.5f * (ab.x * ab.x + ab.y * ab.y + ca.x * ca.x));
    }
    {
        int bin = binof(ca.y);
        int pos = g_binstart[row][bin] + atomicAdd(&g_cursor[row][bin], 1);
        dst[pos] = make_float4(ca.y, bc.x, bc.y,
                               0.5f * (ca.y * ca.y + bc.x * bc.x + bc.y * bc.y));
    }
}

// Phase 1 (per-warp windows) + block-local exact phase 2 + block reduction.
__global__ __launch_bounds__(BT) void chamfer_kernel() {
    __shared__ int    sbs[NB + 1];
    __shared__ float4 qbuf[BT];
    __shared__ float  sdist[BT];
    __shared__ int    slist[BT];
    __shared__ float  smin[BT];
    __shared__ int    scount;

    int blk = blockIdx.x;                 // 1024 blocks
    int dir = blk >> 9;
    int b   = (blk >> 5) & 15;
    int qt  = blk & 31;                   // 32 query tiles of 128
    int tid = threadIdx.x;
    int lane = tid & 31;

    int qRow  = dir ? (16 + b) : b;
    int dbRow = dir ? b : (16 + b);
    const float4* db = g_sorted + (size_t)dbRow * NP;

    for (int k = tid; k <= NB; k += BT) sbs[k] = g_binstart[dbRow][k];
    if (tid == 0) scount = 0;
    float4 q = g_sorted[(size_t)qRow * NP + qt * BT + tid];
    qbuf[tid] = q;
    __syncthreads();

    // Warp-uniform window over this warp's 32 x-adjacent queries.
    unsigned myBin = (unsigned)binof(q.x);
    int kL = (int)__reduce_min_sync(FULLM, myBin);
    int kR = (int)__reduce_max_sync(FULLM, myBin);
    while (sbs[kR + 1] - sbs[kL] < WMINW && (kL > 0 || kR < NB - 1)) {
        if (kL > 0) kL--;
        if (kR < NB - 1) kR++;
    }
    int lo = sbs[kL], hi = sbs[kR + 1];

    // min over window of t_j = 0.5|s_j|^2 - q.s_j  (broadcast LDG, MLP 4)
    float m0 = 1e30f, m1 = 1e30f, m2 = 1e30f, m3 = 1e30f;
    int j = lo;
    #pragma unroll 2
    for (; j + 4 <= hi; j += 4) {
        float4 p0 = __ldg(&db[j]);
        float4 p1 = __ldg(&db[j + 1]);
        float4 p2 = __ldg(&db[j + 2]);
        float4 p3 = __ldg(&db[j + 3]);
        m0 = fminf(m0, fmaf(-q.x, p0.x, fmaf(-q.y, p0.y, fmaf(-q.z, p0.z, p0.w))));
        m1 = fminf(m1, fmaf(-q.x, p1.x, fmaf(-q.y, p1.y, fmaf(-q.z, p1.z, p1.w))));
        m2 = fminf(m2, fmaf(-q.x, p2.x, fmaf(-q.y, p2.y, fmaf(-q.z, p2.z, p2.w))));
        m3 = fminf(m3, fmaf(-q.x, p3.x, fmaf(-q.y, p3.y, fmaf(-q.z, p3.z, p3.w))));
    }
    for (; j < hi; ++j) {
        float4 p0 = __ldg(&db[j]);
        m0 = fminf(m0, fmaf(-q.x, p0.x, fmaf(-q.y, p0.y, fmaf(-q.z, p0.z, p0.w))));
    }
    float m = fminf(fminf(m0, m1), fminf(m2, m3));

    // Exact per-lane exclusion bound at bin-edge window boundaries.
    float thr   = q.w + m;                      // 0.5 * d^2 upper bound
    float edgeL = LOV + (float)kL * WBIN;
    float edgeR = LOV + (float)(kR + 1) * WBIN;
    float gl = fmaxf(q.x - edgeL, 0.0f);
    float gr = fmaxf(edgeR - q.x, 0.0f);
    bool doneL = (kL == 0)      || (0.5f * gl * gl >= thr);
    bool doneR = (kR == NB - 1) || (0.5f * gr * gr >= thr);

    sdist[tid] = sqrtf(1e-6f + fmaxf(2.0f * thr, 0.0f));

    bool need = !(doneL && doneR);
    unsigned mk = __ballot_sync(FULLM, need);
    int nneed = __popc(mk);
    if (nneed) {
        int base = 0;
        if (lane == 0) base = atomicAdd(&scount, nneed);
        base = __shfl_sync(FULLM, base, 0);
        if (need) {
            int rank = __popc(mk & ((1u << lane) - 1));
            slist[base + rank] = tid;
            smin[base + rank] = m;
        }
    }
    __syncthreads();

    // Block-local phase 2: one warp per spilled query, exact range scan.
    int ns = scount;
    int wid = tid >> 5;
    for (int i = wid; i < ns; i += BT / 32) {
        int t = slist[i];
        float mm = smin[i];
        float4 q2 = qbuf[t];
        float d1 = sqrtf(fmaxf(2.0f * (q2.w + mm), 0.0f)) * 1.0005f + 1e-5f;
        int lo2 = sbs[binof(q2.x - d1)];
        int hi2 = sbs[binof(q2.x + d1) + 1];
        for (int jj = lo2 + lane; jj < hi2; jj += 32) {
            float4 p = __ldg(&db[jj]);
            mm = fminf(mm, fmaf(-q2.x, p.x, fmaf(-q2.y, p.y, fmaf(-q2.z, p.z, p.w))));
        }
        #pragma unroll
        for (int o = 16; o; o >>= 1)
            mm = fminf(mm, __shfl_xor_sync(FULLM, mm, o));
        if (lane == 0)
            sdist[t] = sqrtf(1e-6f + fmaxf(2.0f * (q2.w + mm), 0.0f));
    }
    __syncthreads();

    // Deterministic fixed-tree block reduction.
    #pragma unroll
    for (int st = BT / 2; st > 0; st >>= 1) {
        if (tid < st) sdist[tid] += sdist[tid + st];
        __syncthreads();
    }
    if (tid == 0) g_partial[blk] = sdist[0];
}

__global__ __launch_bounds__(512) void finalize_kernel(float* __restrict__ out) {
    __shared__ float s[512];
    int tid = threadIdx.x;
    s[tid] = g_partial[tid] + g_partial[tid + 512];
    __syncthreads();
    #pragma unroll
    for (int st = 256; st > 0; st >>= 1) {
        if (tid < st) s[tid] += s[tid + st];
        __syncthreads();
    }
    if (tid == 0) out[0] = s[0] * (1.0f / (float)TOTAL);
}

extern "C" void kernel_launch(void* const* d_in, const int* in_sizes, int n_in,
                              void* d_out, int out_size) {
    const float* x = (const float*)d_in[0];
    const float* y = (const float*)d_in[1];
    float* out = (float*)d_out;

    hist_kernel<<<256, 256>>>(x, y);
    prefix_kernel<<<ROWS, NB>>>();
    scatter_kernel<<<256, 256>>>(x, y);
    chamfer_kernel<<<CBLOCKS, BT>>>();
    finalize_kernel<<<1, 512>>>(out);
}

// round 7
// speedup vs baseline: 1.1617x; 1.1617x over previous
#include <cuda_runtime.h>
#include <math.h>

#define NP     4096
#define TOTAL  65536              // points per tensor (16*4096)
#define ROWS   32                 // rows: 0-15 = x batches, 16-31 = y batches
#define NB     256
#define LOV    (-5.0f)
#define HIV    (5.0f)
#define WBIN   ((HIV - LOV) / NB)
#define INVW   ((float)NB / (HIV - LOV))
#define PAD    4                  // bins of margin each side (~0.156)
#define WMIN   384                // min pts in a warp window (tails)
#define WCAP   1792               // staged window cap (28 KB)
#define BT     128                // threads per chamfer block
#define QPB    256                // queries per block (Q=2 per thread)
#define NBLK   (2 * TOTAL / QPB)  // 512
#define FULLM  0xFFFFFFFFu

__device__ float4 g_sorted[2 * TOTAL];
__device__ int    g_hist8[ROWS][8][NB];
__device__ int    g_cursor[ROWS][NB];
__device__ int    g_binstart[ROWS][NB + 1];
__device__ float  g_partial[NBLK];

__device__ __forceinline__ int binof(float v) {
    int b = (int)((v - LOV) * INVW);
    return min(max(b, 0), NB - 1);
}

__global__ __launch_bounds__(256) void hist_kernel(const float* __restrict__ x,
                                                   const float* __restrict__ y) {
    int row = blockIdx.x >> 3, seg = blockIdx.x & 7;
    const float* src = ((row >= 16) ? y : x) + (size_t)(row & 15) * NP * 3;
    __shared__ int h[NB];
    int tid = threadIdx.x;
    h[tid] = 0;
    __syncthreads();
    int p0 = seg * 512 + tid * 2;
    atomicAdd(&h[binof(src[3 * p0])], 1);
    atomicAdd(&h[binof(src[3 * (p0 + 1)])], 1);
    __syncthreads();
    g_hist8[row][seg][tid] = h[tid];
}

__global__ __launch_bounds__(NB) void prefix_kernel() {
    int row = blockIdx.x, tid = threadIdx.x;
    __shared__ int s[NB];
    int v = 0;
    #pragma unroll
    for (int k = 0; k < 8; k++) v += g_hist8[row][k][tid];
    s[tid] = v;
    __syncthreads();
    #pragma unroll
    for (int off = 1; off < NB; off <<= 1) {
        int t = (tid >= off) ? s[tid - off] : 0;
        __syncthreads();
        s[tid] += t;
        __syncthreads();
    }
    g_binstart[row][tid] = s[tid] - v;
    g_cursor[row][tid] = 0;
    if (tid == NB - 1) g_binstart[row][NB] = s[tid];
}

__global__ __launch_bounds__(256) void scatter_kernel(const float* __restrict__ x,
                                                      const float* __restrict__ y) {
    int row = blockIdx.x >> 3, seg = blockIdx.x & 7;
    const float* src = ((row >= 16) ? y : x) + (size_t)(row & 15) * NP * 3;
    int p0 = seg * 512 + threadIdx.x * 2;
    const float2* s2 = (const float2*)(src + 3 * p0);
    float2 ab = s2[0], ca = s2[1], bc = s2[2];
    float4* dst = g_sorted + (size_t)row * NP;
    {
        int bin = binof(ab.x);
        int pos = g_binstart[row][bin] + atomicAdd(&g_cursor[row][bin], 1);
        dst[pos] = make_float4(ab.x, ab.y, ca.x,
                               0.5f * (ab.x * ab.x + ab.y * ab.y + ca.x * ca.x));
    }
    {
        int bin = binof(ca.y);
        int pos = g_binstart[row][bin] + atomicAdd(&g_cursor[row][bin], 1);
        dst[pos] = make_float4(ca.y, bc.x, bc.y,
                               0.5f * (ca.y * ca.y + bc.x * bc.x + bc.y * bc.y));
    }
}

__global__ __launch_bounds__(BT) void chamfer_kernel() {
    __shared__ int    sbs[NB + 1];
    __shared__ float4 swin[WCAP];
    __shared__ float4 qbuf[QPB];
    __shared__ float  sdist[QPB];
    __shared__ int    slist[QPB];
    __shared__ float  smin[QPB];
    __shared__ int    scount;
    __shared__ int    wKL[BT / 32], wKR[BT / 32];
    __shared__ int    bWinLo, bWinCnt;

    int blk = blockIdx.x;                 // 512 blocks
    int dir = blk >> 8;
    int b   = (blk >> 4) & 15;
    int qt  = blk & 15;
    int tid = threadIdx.x;
    int lane = tid & 31;
    int wid  = tid >> 5;

    int qRow  = dir ? (16 + b) : b;
    int dbRow = dir ? b : (16 + b);
    const float4* db = g_sorted + (size_t)dbRow * NP;

    for (int k = tid; k <= NB; k += BT) sbs[k] = g_binstart[dbRow][k];
    if (tid == 0) scount = 0;

    // Two consecutive queries per thread.
    const float4* qArr = g_sorted + (size_t)qRow * NP + qt * QPB;
    float4 q0 = qArr[2 * tid];
    float4 q1 = qArr[2 * tid + 1];
    qbuf[2 * tid]     = q0;
    qbuf[2 * tid + 1] = q1;
    __syncthreads();

    // Warp window: span of the warp's 64 queries, padded, count-extended.
    int b0 = binof(q0.x), b1 = binof(q1.x);
    int kL = (int)__reduce_min_sync(FULLM, (unsigned)min(b0, b1));
    int kR = (int)__reduce_max_sync(FULLM, (unsigned)max(b0, b1));
    kL = max(kL - PAD, 0);
    kR = min(kR + PAD, NB - 1);
    while (sbs[kR + 1] - sbs[kL] < WMIN && (kL > 0 || kR < NB - 1)) {
        if (kL > 0) kL--;
        if (kR < NB - 1) kR++;
    }
    if (lane == 0) { wKL[wid] = kL; wKR[wid] = kR; }
    __syncthreads();

    // Block window = union of warp windows, capped at WCAP (right trim).
    if (tid == 0) {
        int kLb = min(min(wKL[0], wKL[1]), min(wKL[2], wKL[3]));
        int kRb = max(max(wKR[0], wKR[1]), max(wKR[2], wKR[3]));
        int lo  = sbs[kLb];
        bWinLo  = lo;
        bWinCnt = min(sbs[kRb + 1] - lo, WCAP);
    }
    __syncthreads();
    int winLo = bWinLo, winCnt = bWinCnt;

    // Stage block window to smem (coalesced).
    for (int j = tid; j < winCnt; j += BT) swin[j] = db[winLo + j];
    __syncthreads();

    // Warp sub-range within the staged window.
    int sLo = max(sbs[kL] - winLo, 0);
    int sHi = min(sbs[kR + 1] - winLo, winCnt);
    bool clampedL = (sbs[kL] < winLo);
    bool clampedR = (sbs[kR + 1] > winLo + winCnt);

    float a0 = 1e30f, a1 = 1e30f, c0 = 1e30f, c1 = 1e30f;
    int j = sLo;
    #pragma unroll 2
    for (; j + 2 <= sHi; j += 2) {
        float4 p0 = swin[j];
        float4 p1 = swin[j + 1];
        a0 = fminf(a0, fmaf(-q0.x, p0.x, fmaf(-q0.y, p0.y, fmaf(-q0.z, p0.z, p0.w))));
        c0 = fminf(c0, fmaf(-q1.x, p0.x, fmaf(-q1.y, p0.y, fmaf(-q1.z, p0.z, p0.w))));
        a1 = fminf(a1, fmaf(-q0.x, p1.x, fmaf(-q0.y, p1.y, fmaf(-q0.z, p1.z, p1.w))));
        c1 = fminf(c1, fmaf(-q1.x, p1.x, fmaf(-q1.y, p1.y, fmaf(-q1.z, p1.z, p1.w))));
    }
    if (j < sHi) {
        float4 p0 = swin[j];
        a0 = fminf(a0, fmaf(-q0.x, p0.x, fmaf(-q0.y, p0.y, fmaf(-q0.z, p0.z, p0.w))));
        c0 = fminf(c0, fmaf(-q1.x, p0.x, fmaf(-q1.y, p0.y, fmaf(-q1.z, p0.z, p0.w))));
    }
    float m0 = fminf(a0, a1);
    float m1 = fminf(c0, c1);

    // Exact per-lane bound check at warp-window bin edges.
    float edgeL = LOV + (float)kL * WBIN;
    float edgeR = LOV + (float)(kR + 1) * WBIN;

    auto finish = [&](float4 q, float m, int slot) {
        float thr = q.w + m;
        float gl = fmaxf(q.x - edgeL, 0.0f);
        float gr = fmaxf(edgeR - q.x, 0.0f);
        bool dL = !clampedL && ((kL == 0)      || (0.5f * gl * gl >= thr));
        bool dR = !clampedR && ((kR == NB - 1) || (0.5f * gr * gr >= thr));
        sdist[slot] = sqrtf(1e-6f + fmaxf(2.0f * thr, 0.0f));
        bool need = !(dL && dR);
        unsigned mk = __ballot_sync(FULLM, need);
        int nneed = __popc(mk);
        if (nneed) {
            int base = 0;
            if (lane == 0) base = atomicAdd(&scount, nneed);
            base = __shfl_sync(FULLM, base, 0);
            if (need) {
                int rank = __popc(mk & ((1u << lane) - 1));
                slist[base + rank] = slot;
                smin[base + rank] = m;
            }
        }
    };
    finish(q0, m0, 2 * tid);
    finish(q1, m1, 2 * tid + 1);
    __syncthreads();

    // Block-local exact phase 2: one warp per spilled query (global LDG).
    int ns = scount;
    for (int i = wid; i < ns; i += BT / 32) {
        int t = slist[i];
        float mm = smin[i];
        float4 q2 = qbuf[t];
        float d1 = sqrtf(fmaxf(2.0f * (q2.w + mm), 0.0f)) * 1.0005f + 1e-5f;
        int lo2 = sbs[binof(q2.x - d1)];
        int hi2 = sbs[binof(q2.x + d1) + 1];
        for (int jj = lo2 + lane; jj < hi2; jj += 32) {
            float4 p = __ldg(&db[jj]);
            mm = fminf(mm, fmaf(-q2.x, p.x, fmaf(-q2.y, p.y, fmaf(-q2.z, p.z, p.w))));
        }
        #pragma unroll
        for (int o = 16; o; o >>= 1)
            mm = fminf(mm, __shfl_xor_sync(FULLM, mm, o));
        if (lane == 0)
            sdist[t] = sqrtf(1e-6f + fmaxf(2.0f * (q2.w + mm), 0.0f));
    }
    __syncthreads();

    // Deterministic fixed-tree reduction over the block's 256 distances.
    float v = sdist[tid] + sdist[tid + BT];
    __syncthreads();
    sdist[tid] = v;
    __syncthreads();
    #pragma unroll
    for (int st = BT / 2; st > 0; st >>= 1) {
        if (tid < st) sdist[tid] += sdist[tid + st];
        __syncthreads();
    }
    if (tid == 0) g_partial[blk] = sdist[0];
}

__global__ __launch_bounds__(256) void finalize_kernel(float* __restrict__ out) {
    __shared__ float s[256];
    int tid = threadIdx.x;
    s[tid] = g_partial[tid] + g_partial[tid + 256];
    __syncthreads();
    #pragma unroll
    for (int st = 128; st > 0; st >>= 1) {
        if (tid < st) s[tid] += s[tid + st];
        __syncthreads();
    }
    if (tid == 0) out[0] = s[0] * (1.0f / (float)TOTAL);
}

extern "C" void kernel_launch(void* const* d_in, const int* in_sizes, int n_in,
                              void* d_out, int out_size) {
    const float* x = (const float*)d_in[0];
    const float* y = (const float*)d_in[1];
    float* out = (float*)d_out;

    hist_kernel<<<256, 256>>>(x, y);
    prefix_kernel<<<ROWS, NB>>>();
    scatter_kernel<<<256, 256>>>(x, y);
    chamfer_kernel<<<NBLK, BT>>>();
    finalize_kernel<<<1, 256>>>(out);
}

// round 8
// speedup vs baseline: 1.3415x; 1.1547x over previous
#include <cuda_runtime.h>
#include <math.h>

#define NP     4096
#define TOTAL  65536              // points per tensor (16*4096)
#define ROWS   32                 // rows: 0-15 = x batches, 16-31 = y batches
#define NB     256
#define LOV    (-5.0f)
#define HIV    (5.0f)
#define WBIN   ((HIV - LOV) / NB)
#define INVW   ((float)NB / (HIV - LOV))
#define PAD    3                  // bins of margin each side (~0.117)
#define WMIN   384                // min pts in a warp window
#define WCAP   1536               // staged window cap (24 KB)
#define BT     128                // threads per chamfer block
#define QPB    128                // queries per block (Q=1)
#define NBLK   (2 * TOTAL / QPB)  // 1024
#define FULLM  0xFFFFFFFFu

__device__ float4 g_sorted[2 * TOTAL];
__device__ int    g_hist8[ROWS][8][NB];
__device__ int    g_cursor[ROWS][NB];
__device__ int    g_binstart[ROWS][NB + 1];
__device__ float  g_partial[NBLK];

__device__ __forceinline__ int binof(float v) {
    int b = (int)((v - LOV) * INVW);
    return min(max(b, 0), NB - 1);
}

__global__ __launch_bounds__(256) void hist_kernel(const float* __restrict__ x,
                                                   const float* __restrict__ y) {
    int row = blockIdx.x >> 3, seg = blockIdx.x & 7;
    const float* src = ((row >= 16) ? y : x) + (size_t)(row & 15) * NP * 3;
    __shared__ int h[NB];
    int tid = threadIdx.x;
    h[tid] = 0;
    __syncthreads();
    int p0 = seg * 512 + tid * 2;
    atomicAdd(&h[binof(src[3 * p0])], 1);
    atomicAdd(&h[binof(src[3 * (p0 + 1)])], 1);
    __syncthreads();
    g_hist8[row][seg][tid] = h[tid];
}

__global__ __launch_bounds__(NB) void prefix_kernel() {
    int row = blockIdx.x, tid = threadIdx.x;
    __shared__ int s[NB];
    int v = 0;
    #pragma unroll
    for (int k = 0; k < 8; k++) v += g_hist8[row][k][tid];
    s[tid] = v;
    __syncthreads();
    #pragma unroll
    for (int off = 1; off < NB; off <<= 1) {
        int t = (tid >= off) ? s[tid - off] : 0;
        __syncthreads();
        s[tid] += t;
        __syncthreads();
    }
    g_binstart[row][tid] = s[tid] - v;
    g_cursor[row][tid] = 0;
    if (tid == NB - 1) g_binstart[row][NB] = s[tid];
}

__global__ __launch_bounds__(256) void scatter_kernel(const float* __restrict__ x,
                                                      const float* __restrict__ y) {
    int row = blockIdx.x >> 3, seg = blockIdx.x & 7;
    const float* src = ((row >= 16) ? y : x) + (size_t)(row & 15) * NP * 3;
    int p0 = seg * 512 + threadIdx.x * 2;
    const float2* s2 = (const float2*)(src + 3 * p0);
    float2 ab = s2[0], ca = s2[1], bc = s2[2];
    float4* dst = g_sorted + (size_t)row * NP;
    {
        int bin = binof(ab.x);
        int pos = g_binstart[row][bin] + atomicAdd(&g_cursor[row][bin], 1);
        dst[pos] = make_float4(ab.x, ab.y, ca.x,
                               0.5f * (ab.x * ab.x + ab.y * ab.y + ca.x * ca.x));
    }
    {
        int bin = binof(ca.y);
        int pos = g_binstart[row][bin] + atomicAdd(&g_cursor[row][bin], 1);
        dst[pos] = make_float4(ca.y, bc.x, bc.y,
                               0.5f * (ca.y * ca.y + bc.x * bc.x + bc.y * bc.y));
    }
}

__global__ __launch_bounds__(BT) void chamfer_kernel() {
    __shared__ int    sbs[NB + 1];
    __shared__ float4 swin[WCAP];
    __shared__ float4 qbuf[QPB];
    __shared__ float  sdist[QPB];
    __shared__ int    slist[QPB];
    __shared__ float  smin[QPB];
    __shared__ int    scount;
    __shared__ int    wKL[4], wKR[4];
    __shared__ int    wScanLo[4], wScanHi[4];   // absolute scanned range per warp
    __shared__ int    bWinLo, bWinCnt;

    int blk = blockIdx.x;                 // 1024 blocks
    int dir = blk >> 9;
    int b   = (blk >> 5) & 15;
    int qt  = blk & 31;                   // 32 tiles of 128 queries
    int tid = threadIdx.x;
    int lane = tid & 31;
    int wid  = tid >> 5;

    int qRow  = dir ? (16 + b) : b;
    int dbRow = dir ? b : (16 + b);
    const float4* db = g_sorted + (size_t)dbRow * NP;

    for (int k = tid; k <= NB; k += BT) sbs[k] = g_binstart[dbRow][k];
    if (tid == 0) scount = 0;

    float4 q = g_sorted[(size_t)qRow * NP + qt * QPB + tid];
    qbuf[tid] = q;
    __syncthreads();

    // Warp window: span of this warp's 32 queries, padded, count-extended.
    int myBin = binof(q.x);
    int kL = (int)__reduce_min_sync(FULLM, (unsigned)myBin);
    int kR = (int)__reduce_max_sync(FULLM, (unsigned)myBin);
    kL = max(kL - PAD, 0);
    kR = min(kR + PAD, NB - 1);
    while (sbs[kR + 1] - sbs[kL] < WMIN && (kL > 0 || kR < NB - 1)) {
        if (kL > 0) kL--;
        if (kR < NB - 1) kR++;
    }
    if (lane == 0) { wKL[wid] = kL; wKR[wid] = kR; }
    __syncthreads();

    // Block window = union of warp windows, capped (right trim).
    if (tid == 0) {
        int kLb = min(min(wKL[0], wKL[1]), min(wKL[2], wKL[3]));
        int kRb = max(max(wKR[0], wKR[1]), max(wKR[2], wKR[3]));
        int lo  = sbs[kLb];
        bWinLo  = lo;
        bWinCnt = min(sbs[kRb + 1] - lo, WCAP);
    }
    __syncthreads();
    int winLo = bWinLo, winCnt = bWinCnt;

    // Stage block window (coalesced).
    for (int j = tid; j < winCnt; j += BT) swin[j] = db[winLo + j];

    // Warp sub-range inside the staged window.
    int sLo = max(sbs[kL] - winLo, 0);
    int sHi = min(sbs[kR + 1] - winLo, winCnt);
    bool clampedL = (sbs[kL] < winLo);
    bool clampedR = (sbs[kR + 1] > winLo + winCnt);
    if (lane == 0) { wScanLo[wid] = winLo + sLo; wScanHi[wid] = winLo + sHi; }
    __syncthreads();

    // min over window of t_j = 0.5|s_j|^2 - q.s_j
    float m0 = 1e30f, m1 = 1e30f, m2 = 1e30f, m3 = 1e30f;
    int j = sLo;
    for (; j + 4 <= sHi; j += 4) {
        float4 p0 = swin[j];
        float4 p1 = swin[j + 1];
        float4 p2 = swin[j + 2];
        float4 p3 = swin[j + 3];
        m0 = fminf(m0, fmaf(-q.x, p0.x, fmaf(-q.y, p0.y, fmaf(-q.z, p0.z, p0.w))));
        m1 = fminf(m1, fmaf(-q.x, p1.x, fmaf(-q.y, p1.y, fmaf(-q.z, p1.z, p1.w))));
        m2 = fminf(m2, fmaf(-q.x, p2.x, fmaf(-q.y, p2.y, fmaf(-q.z, p2.z, p2.w))));
        m3 = fminf(m3, fmaf(-q.x, p3.x, fmaf(-q.y, p3.y, fmaf(-q.z, p3.z, p3.w))));
    }
    for (; j < sHi; ++j) {
        float4 p0 = swin[j];
        m0 = fminf(m0, fmaf(-q.x, p0.x, fmaf(-q.y, p0.y, fmaf(-q.z, p0.z, p0.w))));
    }
    float m = fminf(fminf(m0, m1), fminf(m2, m3));

    // Exact per-lane exclusion bound at warp-window bin edges.
    float thr   = q.w + m;                      // 0.5 * d^2 upper bound
    float edgeL = LOV + (float)kL * WBIN;
    float edgeR = LOV + (float)(kR + 1) * WBIN;
    float gl = fmaxf(q.x - edgeL, 0.0f);
    float gr = fmaxf(edgeR - q.x, 0.0f);
    bool dL = !clampedL && ((kL == 0)      || (0.5f * gl * gl >= thr));
    bool dR = !clampedR && ((kR == NB - 1) || (0.5f * gr * gr >= thr));

    sdist[tid] = sqrtf(1e-6f + fmaxf(2.0f * thr, 0.0f));

    bool need = !(dL && dR);
    unsigned mk = __ballot_sync(FULLM, need);
    int nneed = __popc(mk);
    if (nneed) {
        int base = 0;
        if (lane == 0) base = atomicAdd(&scount, nneed);
        base = __shfl_sync(FULLM, base, 0);
        if (need) {
            int rank = __popc(mk & ((1u << lane) - 1));
            slist[base + rank] = tid;
            smin[base + rank] = m;
        }
    }
    __syncthreads();

    // Block-local exact phase 2: one warp per spilled query; skip the range
    // that query's warp already scanned.
    int ns = scount;
    for (int i = wid; i < ns; i += BT / 32) {
        int t = slist[i];
        float mm = smin[i];
        float4 q2 = qbuf[t];
        int w2 = t >> 5;
        int skLo = wScanLo[w2], skHi = wScanHi[w2];

        float d1 = sqrtf(fmaxf(2.0f * (q2.w + mm), 0.0f)) * 1.0005f + 1e-5f;
        int lo2 = sbs[binof(q2.x - d1)];
        int hi2 = sbs[binof(q2.x + d1) + 1];

        // Left part: [lo2, min(hi2, skLo))
        int hA = min(hi2, skLo);
        for (int jj = lo2 + lane; jj < hA; jj += 32) {
            float4 p = __ldg(&db[jj]);
            mm = fminf(mm, fmaf(-q2.x, p.x, fmaf(-q2.y, p.y, fmaf(-q2.z, p.z, p.w))));
        }
        // Right part: [max(lo2, skHi), hi2)
        int lB = max(lo2, skHi);
        for (int jj = lB + lane; jj < hi2; jj += 32) {
            float4 p = __ldg(&db[jj]);
            mm = fminf(mm, fmaf(-q2.x, p.x, fmaf(-q2.y, p.y, fmaf(-q2.z, p.z, p.w))));
        }
        #pragma unroll
        for (int o = 16; o; o >>= 1)
            mm = fminf(mm, __shfl_xor_sync(FULLM, mm, o));
        if (lane == 0)
            sdist[t] = sqrtf(1e-6f + fmaxf(2.0f * (q2.w + mm), 0.0f));
    }
    __syncthreads();

    // Deterministic fixed-tree reduction over the block's 128 distances.
    #pragma unroll
    for (int st = BT / 2; st > 0; st >>= 1) {
        if (tid < st) sdist[tid] += sdist[tid + st];
        __syncthreads();
    }
    if (tid == 0) g_partial[blk] = sdist[0];
}

__global__ __launch_bounds__(512) void finalize_kernel(float* __restrict__ out) {
    __shared__ float s[512];
    int tid = threadIdx.x;
    s[tid] = g_partial[tid] + g_partial[tid + 512];
    __syncthreads();
    #pragma unroll
    for (int st = 256; st > 0; st >>= 1) {
        if (tid < st) s[tid] += s[tid + st];
        __syncthreads();
    }
    if (tid == 0) out[0] = s[0] * (1.0f / (float)TOTAL);
}

extern "C" void kernel_launch(void* const* d_in, const int* in_sizes, int n_in,
                              void* d_out, int out_size) {
    const float* x = (const float*)d_in[0];
    const float* y = (const float*)d_in[1];
    float* out = (float*)d_out;

    hist_kernel<<<256, 256>>>(x, y);
    prefix_kernel<<<ROWS, NB>>>();
    scatter_kernel<<<256, 256>>>(x, y);
    chamfer_kernel<<<NBLK, BT>>>();
    finalize_kernel<<<1, 512>>>(out);
}